// round 16
// baseline (speedup 1.0000x reference)
#include <cuda_runtime.h>
#include <cuda_fp16.h>

#define N_NODES  100000
#define IN_DIM   256
#define OUT_DIM  128
#define FEAT_NNZ 1000000
#define ADJ_NNZ  1600000

#define TILE      1024
#define NBLK      ((N_NODES + TILE - 1) / TILE)   // 98

#define T         256
#define FBH       ((FEAT_NNZ / 2 + T - 1) / T)    // feat blocks, 2 entries/thread
#define ABH       ((ADJ_NNZ  / 2 + T - 1) / T)    // adj  blocks, 2 entries/thread
#define ROWS_GRID ((N_NODES + 7) / 8)             // 12500 spmm row blocks

// ---------------------------------------------------------------------------
// Scratch (__device__ globals; zero-initialized at module load; referenced
// ONLY from device code). cnt arrays are re-zeroed by scan_p3 after use so
// every graph replay sees identical initial state.
// ---------------------------------------------------------------------------
__device__ uint2  g_xw2[(size_t)N_NODES * 32];            // XW fp16, 25.6 MB

__device__ int    g_feat_cnt [N_NODES];
__device__ int    g_feat_ptr [N_NODES + 1];
__device__ int    g_feat_rank[FEAT_NNZ];                  // within-row rank
__device__ float2 g_feat_csr [FEAT_NNZ];                  // {val, (col*32) bits}
__device__ int    g_feat_bsum[NBLK];

__device__ int    g_adj_cnt [N_NODES];
__device__ int    g_adj_ptr [N_NODES + 1];
__device__ int    g_adj_rank[ADJ_NNZ];
__device__ uint2  g_adj_csr [ADJ_NNZ];                    // {val as half2-dup, col*32}
__device__ int    g_adj_bsum[NBLK];

// ---------------------------------------------------------------------------
// 1. Fused row histogram, 2 entries/thread, capturing each entry's
//    within-row rank (the atomic's return). Scatter then needs NO atomics.
// ---------------------------------------------------------------------------
__global__ void hist_both_kernel(const int2* __restrict__ feat_rows2,
                                 const int2* __restrict__ adj_rows2) {
    if (blockIdx.x < FBH) {
        int i = blockIdx.x * T + threadIdx.x;      // pair index
        int base = i * 2;
        if (base < FEAT_NNZ) {                     // FEAT_NNZ even -> both valid
            int2 r = __ldg(&feat_rows2[i]);
            g_feat_rank[base]     = atomicAdd(&g_feat_cnt[r.x], 1);
            g_feat_rank[base + 1] = atomicAdd(&g_feat_cnt[r.y], 1);
        }
    } else {
        int i = (blockIdx.x - FBH) * T + threadIdx.x;
        int base = i * 2;
        if (base < ADJ_NNZ) {                      // ADJ_NNZ even -> both valid
            int2 r = __ldg(&adj_rows2[i]);
            g_adj_rank[base]     = atomicAdd(&g_adj_cnt[r.x], 1);
            g_adj_rank[base + 1] = atomicAdd(&g_adj_cnt[r.y], 1);
        }
    }
}

// ---------------------------------------------------------------------------
// 2a. Scan phase 1 (fused): per-tile sums of cnt. First NBLK blocks = feat.
// ---------------------------------------------------------------------------
__global__ void scan_p1_kernel() {
    int which = (blockIdx.x >= NBLK);
    int blk   = which ? (blockIdx.x - NBLK) : blockIdx.x;
    const int* __restrict__ cnt = which ? g_adj_cnt  : g_feat_cnt;
    int* __restrict__ bsum      = which ? g_adj_bsum : g_feat_bsum;

    __shared__ int s[TILE];
    int t   = threadIdx.x;
    int idx = blk * TILE + t;
    s[t] = (idx < N_NODES) ? cnt[idx] : 0;
    __syncthreads();
    for (int off = TILE >> 1; off > 0; off >>= 1) {
        if (t < off) s[t] += s[t + off];
        __syncthreads();
    }
    if (t == 0) bsum[blk] = s[0];
}

// ---------------------------------------------------------------------------
// 2b. Scan phase 3 (fused, self-offsetting): tile offset via masked block
//     reduction over bsum, inclusive tile scan, write ptr, zero cnt.
// ---------------------------------------------------------------------------
__global__ void scan_p3_kernel() {
    int which = (blockIdx.x >= NBLK);
    int blk   = which ? (blockIdx.x - NBLK) : blockIdx.x;
    int* __restrict__ cnt        = which ? g_adj_cnt  : g_feat_cnt;
    const int* __restrict__ bsum = which ? g_adj_bsum : g_feat_bsum;
    int* __restrict__ ptr        = which ? g_adj_ptr  : g_feat_ptr;

    __shared__ int s[TILE];
    __shared__ int red[128];
    int t = threadIdx.x;

    if (t < 128) red[t] = (t < NBLK && t < blk) ? bsum[t] : 0;
    __syncthreads();
    for (int off = 64; off > 0; off >>= 1) {
        if (t < off) red[t] += red[t + off];
        __syncthreads();
    }
    int boff = red[0];
    __syncthreads();

    int idx = blk * TILE + t;
    int v   = (idx < N_NODES) ? cnt[idx] : 0;
    s[t] = v;
    __syncthreads();
    for (int off = 1; off < TILE; off <<= 1) {
        int u = (t >= off) ? s[t - off] : 0;
        __syncthreads();
        s[t] += u;
        __syncthreads();
    }

    if (idx < N_NODES) {
        ptr[idx] = boff + s[t] - v;
        cnt[idx] = 0;                               // replay invariant
    }
    if (blk == NBLK - 1 && t == TILE - 1) ptr[N_NODES] = boff + s[t];
}

// ---------------------------------------------------------------------------
// 3. FUSED scatter: blocks [0, FBH) scatter feat COO, blocks [FBH, FBH+ABH)
//    scatter adj COO. Both are latency-bound with disjoint data, so
//    co-residency overlaps their miss latencies. No atomics (rank-based).
// ---------------------------------------------------------------------------
__global__ void scatter_both_kernel(const float2* __restrict__ feat_vals2,
                                    const int2*   __restrict__ feat_rows2,
                                    const int2*   __restrict__ feat_cols2,
                                    const float2* __restrict__ adj_vals2,
                                    const int2*   __restrict__ adj_rows2,
                                    const int2*   __restrict__ adj_cols2) {
    if (blockIdx.x < FBH) {
        // ---- feat scatter, 2 entries/thread ----
        int i = blockIdx.x * T + threadIdx.x;       // pair index
        int base = i * 2;
        if (base >= FEAT_NNZ) return;               // FEAT_NNZ even -> both valid
        int2   r = __ldg(&feat_rows2[i]);
        int2   c = __ldg(&feat_cols2[i]);
        float2 v = __ldg(&feat_vals2[i]);
        int2   k = __ldg(&((const int2*)g_feat_rank)[i]);
        int p0 = __ldg(&g_feat_ptr[r.x]) + k.x;
        int p1 = __ldg(&g_feat_ptr[r.y]) + k.y;
        g_feat_csr[p0] = make_float2(v.x, __int_as_float(c.x * 32));
        g_feat_csr[p1] = make_float2(v.y, __int_as_float(c.y * 32));
    } else {
        // ---- adj scatter, 2 entries/thread ----
        int i = (blockIdx.x - FBH) * T + threadIdx.x;
        int base = i * 2;
        if (base >= ADJ_NNZ) return;                // ADJ_NNZ even -> both valid
        int2   r = __ldg(&adj_rows2[i]);
        int2   c = __ldg(&adj_cols2[i]);
        float2 v = __ldg(&adj_vals2[i]);
        int2   k = __ldg(&((const int2*)g_adj_rank)[i]);
        int p0 = __ldg(&g_adj_ptr[r.x]) + k.x;
        int p1 = __ldg(&g_adj_ptr[r.y]) + k.y;
        __half2 h0 = __float2half2_rn(v.x);
        __half2 h1 = __float2half2_rn(v.y);
        g_adj_csr[p0] = make_uint2(*reinterpret_cast<unsigned int*>(&h0),
                                   (unsigned int)(c.x * 32));
        g_adj_csr[p1] = make_uint2(*reinterpret_cast<unsigned int*>(&h1),
                                   (unsigned int)(c.y * 32));
    }
}

// ---------------------------------------------------------------------------
// 4. SpMM1: XW[row,:] = sum_e val_e * W[col_e,:] (fp32 accum, fp16 store).
//    Warp per row; lane owns 4 OUT cols; W (128 KB) L1-resident.
// ---------------------------------------------------------------------------
__global__ void spmm1_csr_kernel(const float4* __restrict__ W4) {
    int row  = blockIdx.x * (T >> 5) + (threadIdx.x >> 5);
    if (row >= N_NODES) return;
    int lane = threadIdx.x & 31;

    int s = g_feat_ptr[row];
    int e = g_feat_ptr[row + 1];

    float4 acc = make_float4(0.f, 0.f, 0.f, 0.f);
    int j = s;
    for (; j + 2 <= e; j += 2) {
        float2 vc0 = __ldg(&g_feat_csr[j]);
        float2 vc1 = __ldg(&g_feat_csr[j + 1]);
        float4 w0 = __ldg(&W4[__float_as_int(vc0.y) + lane]);   // coloff pre-*32
        float4 w1 = __ldg(&W4[__float_as_int(vc1.y) + lane]);
        acc.x += vc0.x * w0.x + vc1.x * w1.x;
        acc.y += vc0.x * w0.y + vc1.x * w1.y;
        acc.z += vc0.x * w0.z + vc1.x * w1.z;
        acc.w += vc0.x * w0.w + vc1.x * w1.w;
    }
    for (; j < e; j++) {
        float2 vc = __ldg(&g_feat_csr[j]);
        float4 w = __ldg(&W4[__float_as_int(vc.y) + lane]);
        acc.x += vc.x * w.x;
        acc.y += vc.x * w.y;
        acc.z += vc.x * w.z;
        acc.w += vc.x * w.w;
    }
    __half2 h0 = __floats2half2_rn(acc.x, acc.y);
    __half2 h1 = __floats2half2_rn(acc.z, acc.w);
    uint2 packed;
    packed.x = *reinterpret_cast<unsigned int*>(&h0);
    packed.y = *reinterpret_cast<unsigned int*>(&h1);
    g_xw2[(size_t)row * 32 + lane] = packed;
}

// ---------------------------------------------------------------------------
// 5. SpMM2 — half2 inner loop, paired uint4 csr loads (2 edges per LDG,
//    alignment prologue), fp32 flush per 4-edge chunk. Fused bias+ReLU.
// ---------------------------------------------------------------------------
__global__ void spmm2_csr_kernel(float4* __restrict__ out4,
                                 const float4* __restrict__ bias4) {
    int row  = blockIdx.x * (T >> 5) + (threadIdx.x >> 5);
    if (row >= N_NODES) return;
    int lane = threadIdx.x & 31;

    int s = g_adj_ptr[row];
    int e = g_adj_ptr[row + 1];

    float4 acc = make_float4(0.f, 0.f, 0.f, 0.f);
    int j = s;

    // alignment prologue: make j even so uint4 loads are 16B-aligned
    if ((j & 1) && j < e) {
        uint2 ej = __ldg(&g_adj_csr[j]);
        uint2 xr = __ldg(&g_xw2[ej.y + lane]);
        __half2 vj = *reinterpret_cast<__half2*>(&ej.x);
        float2 f0 = __half22float2(__hmul2(vj, *reinterpret_cast<__half2*>(&xr.x)));
        float2 f1 = __half22float2(__hmul2(vj, *reinterpret_cast<__half2*>(&xr.y)));
        acc.x += f0.x;
        acc.y += f0.y;
        acc.z += f1.x;
        acc.w += f1.y;
        j++;
    }

    for (; j + 4 <= e; j += 4) {
        // 2 uint4 loads cover 4 csr entries (val-half2, coloff interleaved)
        uint4 c01 = __ldg(reinterpret_cast<const uint4*>(&g_adj_csr[j]));
        uint4 c23 = __ldg(reinterpret_cast<const uint4*>(&g_adj_csr[j + 2]));
        uint2 x0 = __ldg(&g_xw2[c01.y + lane]);
        uint2 x1 = __ldg(&g_xw2[c01.w + lane]);
        uint2 x2 = __ldg(&g_xw2[c23.y + lane]);
        uint2 x3 = __ldg(&g_xw2[c23.w + lane]);

        __half2 v0 = *reinterpret_cast<__half2*>(&c01.x);
        __half2 v1 = *reinterpret_cast<__half2*>(&c01.z);
        __half2 v2 = *reinterpret_cast<__half2*>(&c23.x);
        __half2 v3 = *reinterpret_cast<__half2*>(&c23.z);

        // chunk of 4 edges in half2 (cols 0-1 in sA, cols 2-3 in sB)
        __half2 sA = __hmul2(v0, *reinterpret_cast<__half2*>(&x0.x));
        __half2 sB = __hmul2(v0, *reinterpret_cast<__half2*>(&x0.y));
        sA = __hfma2(v1, *reinterpret_cast<__half2*>(&x1.x), sA);
        sB = __hfma2(v1, *reinterpret_cast<__half2*>(&x1.y), sB);
        sA = __hfma2(v2, *reinterpret_cast<__half2*>(&x2.x), sA);
        sB = __hfma2(v2, *reinterpret_cast<__half2*>(&x2.y), sB);
        sA = __hfma2(v3, *reinterpret_cast<__half2*>(&x3.x), sA);
        sB = __hfma2(v3, *reinterpret_cast<__half2*>(&x3.y), sB);

        float2 fA = __half22float2(sA);
        float2 fB = __half22float2(sB);
        acc.x += fA.x;
        acc.y += fA.y;
        acc.z += fB.x;
        acc.w += fB.y;
    }
    for (; j < e; j++) {
        uint2 ej = __ldg(&g_adj_csr[j]);
        uint2 xr = __ldg(&g_xw2[ej.y + lane]);
        __half2 vj = *reinterpret_cast<__half2*>(&ej.x);
        float2 f0 = __half22float2(__hmul2(vj, *reinterpret_cast<__half2*>(&xr.x)));
        float2 f1 = __half22float2(__hmul2(vj, *reinterpret_cast<__half2*>(&xr.y)));
        acc.x += f0.x;
        acc.y += f0.y;
        acc.z += f1.x;
        acc.w += f1.y;
    }

    float4 b = __ldg(&bias4[lane]);
    acc.x = fmaxf(acc.x + b.x, 0.f);
    acc.y = fmaxf(acc.y + b.y, 0.f);
    acc.z = fmaxf(acc.z + b.z, 0.f);
    acc.w = fmaxf(acc.w + b.w, 0.f);
    out4[(size_t)row * 32 + lane] = acc;
}

// ---------------------------------------------------------------------------
extern "C" void kernel_launch(void* const* d_in, const int* in_sizes, int n_in,
                              void* d_out, int out_size) {
    const float* feat_vals = (const float*)d_in[0];
    const int*   feat_rows = (const int*)  d_in[1];
    const int*   feat_cols = (const int*)  d_in[2];
    const float* adj_vals  = (const float*)d_in[3];
    const int*   adj_rows  = (const int*)  d_in[4];
    const int*   adj_cols  = (const int*)  d_in[5];
    const float* weights   = (const float*)d_in[6];
    const float* bias_vec  = (const float*)d_in[7];
    float4* out4 = (float4*)d_out;

    hist_both_kernel<<<FBH + ABH, T>>>((const int2*)feat_rows,
                                       (const int2*)adj_rows);

    scan_p1_kernel<<<2 * NBLK, TILE>>>();
    scan_p3_kernel<<<2 * NBLK, TILE>>>();

    // both scatters co-resident: overlapped miss latency, one less launch
    scatter_both_kernel<<<FBH + ABH, T>>>((const float2*)feat_vals,
                                          (const int2*)feat_rows,
                                          (const int2*)feat_cols,
                                          (const float2*)adj_vals,
                                          (const int2*)adj_rows,
                                          (const int2*)adj_cols);

    spmm1_csr_kernel<<<ROWS_GRID, T>>>((const float4*)weights);

    spmm2_csr_kernel<<<ROWS_GRID, T>>>(out4, (const float4*)bias_vec);
}

// round 17
// speedup vs baseline: 1.1273x; 1.1273x over previous
#include <cuda_runtime.h>
#include <cuda_fp16.h>

#define N_NODES  100000
#define IN_DIM   256
#define OUT_DIM  128
#define FEAT_NNZ 1000000
#define ADJ_NNZ  1600000

#define TILE      1024
#define NBLK      ((N_NODES + TILE - 1) / TILE)   // 98
#define SGRID     (2 * NBLK)                      // 196, all co-resident

#define T         256
#define FBH       ((FEAT_NNZ / 2 + T - 1) / T)    // feat blocks, 2 entries/thread
#define ABH       ((ADJ_NNZ  / 2 + T - 1) / T)    // adj  blocks, 2 entries/thread
#define ROWS_GRID ((N_NODES + 7) / 8)             // 12500 spmm row blocks

// ---------------------------------------------------------------------------
// Scratch (__device__ globals; zero-initialized at module load; referenced
// ONLY from device code). cnt arrays re-zeroed by the scan kernel; scan
// flags re-zeroed by scatter_feat — every replay sees identical state.
// ---------------------------------------------------------------------------
__device__ uint2  g_xw2[(size_t)N_NODES * 32];            // XW fp16, 25.6 MB

__device__ int    g_feat_cnt [N_NODES];
__device__ int    g_feat_ptr [N_NODES + 1];
__device__ int    g_feat_rank[FEAT_NNZ];                  // within-row rank
__device__ float2 g_feat_csr [FEAT_NNZ];                  // {val, (col*32) bits}

__device__ int    g_adj_cnt [N_NODES];
__device__ int    g_adj_ptr [N_NODES + 1];
__device__ int    g_adj_rank[ADJ_NNZ];
__device__ uint2  g_adj_csr [ADJ_NNZ];                    // {val as half2-dup, col*32}

__device__ int    g_bsum[SGRID];                          // tile aggregates
__device__ int    g_flag[SGRID];                          // aggregate-ready flags

// ---------------------------------------------------------------------------
// 1. Fused row histogram, 2 entries/thread, capturing each entry's
//    within-row rank (the atomic's return). Scatter then needs NO atomics.
// ---------------------------------------------------------------------------
__global__ void hist_both_kernel(const int2* __restrict__ feat_rows2,
                                 const int2* __restrict__ adj_rows2) {
    if (blockIdx.x < FBH) {
        int i = blockIdx.x * T + threadIdx.x;      // pair index
        int base = i * 2;
        if (base < FEAT_NNZ) {                     // FEAT_NNZ even -> both valid
            int2 r = __ldg(&feat_rows2[i]);
            g_feat_rank[base]     = atomicAdd(&g_feat_cnt[r.x], 1);
            g_feat_rank[base + 1] = atomicAdd(&g_feat_cnt[r.y], 1);
        }
    } else {
        int i = (blockIdx.x - FBH) * T + threadIdx.x;
        int base = i * 2;
        if (base < ADJ_NNZ) {                      // ADJ_NNZ even -> both valid
            int2 r = __ldg(&adj_rows2[i]);
            g_adj_rank[base]     = atomicAdd(&g_adj_cnt[r.x], 1);
            g_adj_rank[base + 1] = atomicAdd(&g_adj_cnt[r.y], 1);
        }
    }
}

// ---------------------------------------------------------------------------
// 2. ONE-PASS scan (replaces scan_p1 + scan_p3). 2*NBLK blocks, all
//    co-resident (196 x 1024 thr <= 148 SMs x 2). Each block:
//      (i)   inclusive Hillis-Steele over its 1024-tile of cnt
//      (ii)  publishes its tile aggregate (bsum + release flag)
//      (iii) spins on predecessors' flags (one spinning thread each),
//            reduces their aggregates -> tile offset
//      (iv)  writes ptr, zeroes cnt (replay invariant)
//    Flags are reset by scatter_feat (next kernel, stream-ordered).
// ---------------------------------------------------------------------------
__global__ void __launch_bounds__(TILE, 2) scan_onepass_kernel() {
    int gbid  = blockIdx.x;
    int which = (gbid >= NBLK);
    int blk   = which ? (gbid - NBLK) : gbid;
    int mbase = which ? NBLK : 0;                   // this matrix's flag base
    int* __restrict__ cnt = which ? g_adj_cnt : g_feat_cnt;
    int* __restrict__ ptr = which ? g_adj_ptr : g_feat_ptr;

    __shared__ int s[TILE];
    __shared__ int red[128];
    int t = threadIdx.x;

    // (i) inclusive scan over this tile
    int idx = blk * TILE + t;
    int v   = (idx < N_NODES) ? cnt[idx] : 0;
    s[t] = v;
    __syncthreads();
    for (int off = 1; off < TILE; off <<= 1) {
        int u = (t >= off) ? s[t - off] : 0;
        __syncthreads();
        s[t] += u;
        __syncthreads();
    }

    // (ii) publish aggregate (s[TILE-1]) with release ordering
    if (t == 0) {
        atomicExch(&g_bsum[gbid], s[TILE - 1]);     // L2 write, bypasses L1
        __threadfence();
        atomicExch(&g_flag[gbid], 1);
    }

    // (iii) gather predecessor aggregates: thread t handles predecessor t
    int pre = 0;
    if (t < 128) {
        if (t < blk) {
            while (atomicAdd(&g_flag[mbase + t], 0) == 0) { }
            pre = atomicAdd(&g_bsum[mbase + t], 0);
        }
        red[t] = pre;
    }
    __syncthreads();
    for (int off = 64; off > 0; off >>= 1) {
        if (t < off) red[t] += red[t + off];
        __syncthreads();
    }
    int boff = red[0];
    __syncthreads();

    // (iv) write ptr (exclusive prefix), restore cnt = 0
    if (idx < N_NODES) {
        ptr[idx] = boff + s[t] - v;
        cnt[idx] = 0;
    }
    if (blk == NBLK - 1 && t == TILE - 1) {
        ptr[N_NODES] = boff + s[t];
    }
}

// ---------------------------------------------------------------------------
// 3. Feat scatter, 2 entries/thread — no atomics. Also resets the scan
//    flags (first SGRID threads of block 0) for the next graph replay.
// ---------------------------------------------------------------------------
__global__ void scatter_feat_kernel(const float2* __restrict__ feat_vals2,
                                    const int2*   __restrict__ feat_rows2,
                                    const int2*   __restrict__ feat_cols2) {
    if (blockIdx.x == 0 && threadIdx.x < SGRID) {
        g_flag[threadIdx.x] = 0;                    // replay invariant
    }
    int i = blockIdx.x * T + threadIdx.x;           // pair index
    int base = i * 2;
    if (base >= FEAT_NNZ) return;                   // FEAT_NNZ even -> both valid
    int2   r = __ldg(&feat_rows2[i]);
    int2   c = __ldg(&feat_cols2[i]);
    float2 v = __ldg(&feat_vals2[i]);
    int2   k = __ldg(&((const int2*)g_feat_rank)[i]);
    int p0 = __ldg(&g_feat_ptr[r.x]) + k.x;
    int p1 = __ldg(&g_feat_ptr[r.y]) + k.y;
    g_feat_csr[p0] = make_float2(v.x, __int_as_float(c.x * 32));
    g_feat_csr[p1] = make_float2(v.y, __int_as_float(c.y * 32));
}

// ---------------------------------------------------------------------------
// 4. FUSED: blocks [0, ABH) scatter the adj COO into CSR (2 entries/thread,
//    value pre-converted to a duplicated half2, column pre-multiplied by 32);
//    blocks [ABH, ...) run SpMM1 over the complete feat CSR. Disjoint data —
//    latency-bound scatter overlaps with issue-bound SpMM1 (the R12 pairing).
// ---------------------------------------------------------------------------
__global__ void adj_scatter_spmm1_kernel(const float2* __restrict__ adj_vals2,
                                         const int2*   __restrict__ adj_rows2,
                                         const int2*   __restrict__ adj_cols2,
                                         const float4* __restrict__ W4) {
    if (blockIdx.x < ABH) {
        // ---- adj scatter, 2 entries/thread ----
        int i = blockIdx.x * T + threadIdx.x;       // pair index
        int base = i * 2;
        if (base >= ADJ_NNZ) return;                // ADJ_NNZ even -> both valid
        int2   r = __ldg(&adj_rows2[i]);
        int2   c = __ldg(&adj_cols2[i]);
        float2 v = __ldg(&adj_vals2[i]);
        int2   k = __ldg(&((const int2*)g_adj_rank)[i]);
        int p0 = __ldg(&g_adj_ptr[r.x]) + k.x;
        int p1 = __ldg(&g_adj_ptr[r.y]) + k.y;
        __half2 h0 = __float2half2_rn(v.x);
        __half2 h1 = __float2half2_rn(v.y);
        g_adj_csr[p0] = make_uint2(*reinterpret_cast<unsigned int*>(&h0),
                                   (unsigned int)(c.x * 32));
        g_adj_csr[p1] = make_uint2(*reinterpret_cast<unsigned int*>(&h1),
                                   (unsigned int)(c.y * 32));
        return;
    }

    // ---- SpMM1: XW[row,:] = sum_e val_e * W[col_e,:] (fp32, fp16 store) ----
    int b    = blockIdx.x - ABH;
    int row  = b * (T >> 5) + (threadIdx.x >> 5);
    if (row >= N_NODES) return;
    int lane = threadIdx.x & 31;

    int s = g_feat_ptr[row];
    int e = g_feat_ptr[row + 1];

    float4 acc = make_float4(0.f, 0.f, 0.f, 0.f);
    int j = s;
    for (; j + 2 <= e; j += 2) {
        float2 vc0 = __ldg(&g_feat_csr[j]);
        float2 vc1 = __ldg(&g_feat_csr[j + 1]);
        float4 w0 = __ldg(&W4[__float_as_int(vc0.y) + lane]);   // coloff pre-*32
        float4 w1 = __ldg(&W4[__float_as_int(vc1.y) + lane]);
        acc.x += vc0.x * w0.x + vc1.x * w1.x;
        acc.y += vc0.x * w0.y + vc1.x * w1.y;
        acc.z += vc0.x * w0.z + vc1.x * w1.z;
        acc.w += vc0.x * w0.w + vc1.x * w1.w;
    }
    for (; j < e; j++) {
        float2 vc = __ldg(&g_feat_csr[j]);
        float4 w = __ldg(&W4[__float_as_int(vc.y) + lane]);
        acc.x += vc.x * w.x;
        acc.y += vc.x * w.y;
        acc.z += vc.x * w.z;
        acc.w += vc.x * w.w;
    }
    __half2 h0 = __floats2half2_rn(acc.x, acc.y);
    __half2 h1 = __floats2half2_rn(acc.z, acc.w);
    uint2 packed;
    packed.x = *reinterpret_cast<unsigned int*>(&h0);
    packed.y = *reinterpret_cast<unsigned int*>(&h1);
    g_xw2[(size_t)row * 32 + lane] = packed;
}

// ---------------------------------------------------------------------------
// 5. SpMM2 — half2 inner loop (2 HFMA2 per edge, zero converts), chunked
//    fp32 flush every 4 edges for accumulation precision. Fused bias+ReLU.
//    (Exact R12 version.)
// ---------------------------------------------------------------------------
__global__ void spmm2_csr_kernel(float4* __restrict__ out4,
                                 const float4* __restrict__ bias4) {
    int row  = blockIdx.x * (T >> 5) + (threadIdx.x >> 5);
    if (row >= N_NODES) return;
    int lane = threadIdx.x & 31;

    int s = g_adj_ptr[row];
    int e = g_adj_ptr[row + 1];

    float4 acc = make_float4(0.f, 0.f, 0.f, 0.f);
    int j = s;
    for (; j + 4 <= e; j += 4) {
        uint2 e0 = __ldg(&g_adj_csr[j]);
        uint2 e1 = __ldg(&g_adj_csr[j + 1]);
        uint2 e2 = __ldg(&g_adj_csr[j + 2]);
        uint2 e3 = __ldg(&g_adj_csr[j + 3]);
        uint2 x0 = __ldg(&g_xw2[e0.y + lane]);
        uint2 x1 = __ldg(&g_xw2[e1.y + lane]);
        uint2 x2 = __ldg(&g_xw2[e2.y + lane]);
        uint2 x3 = __ldg(&g_xw2[e3.y + lane]);

        __half2 v0 = *reinterpret_cast<__half2*>(&e0.x);
        __half2 v1 = *reinterpret_cast<__half2*>(&e1.x);
        __half2 v2 = *reinterpret_cast<__half2*>(&e2.x);
        __half2 v3 = *reinterpret_cast<__half2*>(&e3.x);

        // chunk of 4 edges in half2 (cols 0-1 in sA, cols 2-3 in sB)
        __half2 sA = __hmul2(v0, *reinterpret_cast<__half2*>(&x0.x));
        __half2 sB = __hmul2(v0, *reinterpret_cast<__half2*>(&x0.y));
        sA = __hfma2(v1, *reinterpret_cast<__half2*>(&x1.x), sA);
        sB = __hfma2(v1, *reinterpret_cast<__half2*>(&x1.y), sB);
        sA = __hfma2(v2, *reinterpret_cast<__half2*>(&x2.x), sA);
        sB = __hfma2(v2, *reinterpret_cast<__half2*>(&x2.y), sB);
        sA = __hfma2(v3, *reinterpret_cast<__half2*>(&x3.x), sA);
        sB = __hfma2(v3, *reinterpret_cast<__half2*>(&x3.y), sB);

        float2 fA = __half22float2(sA);
        float2 fB = __half22float2(sB);
        acc.x += fA.x;
        acc.y += fA.y;
        acc.z += fB.x;
        acc.w += fB.y;
    }
    for (; j < e; j++) {
        uint2 ej = __ldg(&g_adj_csr[j]);
        uint2 xr = __ldg(&g_xw2[ej.y + lane]);
        __half2 vj = *reinterpret_cast<__half2*>(&ej.x);
        float2 f0 = __half22float2(__hmul2(vj, *reinterpret_cast<__half2*>(&xr.x)));
        float2 f1 = __half22float2(__hmul2(vj, *reinterpret_cast<__half2*>(&xr.y)));
        acc.x += f0.x;
        acc.y += f0.y;
        acc.z += f1.x;
        acc.w += f1.y;
    }

    float4 b = __ldg(&bias4[lane]);
    acc.x = fmaxf(acc.x + b.x, 0.f);
    acc.y = fmaxf(acc.y + b.y, 0.f);
    acc.z = fmaxf(acc.z + b.z, 0.f);
    acc.w = fmaxf(acc.w + b.w, 0.f);
    out4[(size_t)row * 32 + lane] = acc;
}

// ---------------------------------------------------------------------------
extern "C" void kernel_launch(void* const* d_in, const int* in_sizes, int n_in,
                              void* d_out, int out_size) {
    const float* feat_vals = (const float*)d_in[0];
    const int*   feat_rows = (const int*)  d_in[1];
    const int*   feat_cols = (const int*)  d_in[2];
    const float* adj_vals  = (const float*)d_in[3];
    const int*   adj_rows  = (const int*)  d_in[4];
    const int*   adj_cols  = (const int*)  d_in[5];
    const float* weights   = (const float*)d_in[6];
    const float* bias_vec  = (const float*)d_in[7];
    float4* out4 = (float4*)d_out;

    hist_both_kernel<<<FBH + ABH, T>>>((const int2*)feat_rows,
                                       (const int2*)adj_rows);

    scan_onepass_kernel<<<SGRID, TILE>>>();

    scatter_feat_kernel<<<FBH, T>>>((const float2*)feat_vals,
                                    (const int2*)feat_rows,
                                    (const int2*)feat_cols);

    adj_scatter_spmm1_kernel<<<ABH + ROWS_GRID, T>>>((const float2*)adj_vals,
                                                     (const int2*)adj_rows,
                                                     (const int2*)adj_cols,
                                                     (const float4*)weights);

    spmm2_csr_kernel<<<ROWS_GRID, T>>>(out4, (const float4*)bias_vec);
}